// round 12
// baseline (speedup 1.0000x reference)
#include <cuda_runtime.h>
#include <cuda_bf16.h>

// UnitarySpectralFilter — FINAL, converged at the HBM/LTS roofline.
//
// y = Re[ ifft( fft(x, n=4) * exp(i*alpha*atan(log(|k|+eps))) ) ]
// n=4, k=[0,.25,-.5,-.25], phi1==phi3, real input. Real-part closed form/row:
//   s02=x0+x2 ; s13=x1+x3 ; a=s02+s13 ; c=s02-s13 ; u=x0-x2 ; v=x1-x3
//   Pre=a*C0+c*C2 ; Qre=a*C0-c*C2
//   out = (Pre+u*C1, Qre+v*C1, Pre-u*C1, Qre-v*C1)
// with C0=cos(alpha*t0)/4, C2=cos(alpha*t2)/4, C1=cos(alpha*t1)/2.
//
// Session evidence (kernel us / DRAM%):
//   R4/R11 grid-stride 8192x256 (this config) : 76.4 / 80.1  <- optimal
//   R8  dual-stream MLP=2                      : 76.8 / 79.9  (tied)
//   R7  +__ldcs/__stcs                         : 79.5 / 77.3  (hints hurt)
//   R10 single-wave persistent                 : 81.3 / 75.6  (lost wave backfill)
//   R6  1 row/thread flat                      : 86.5 / 71.1  (preamble per row)
// All good variants measure 6270-6350 GB/s = sm_103a path-independent LTS cap.
// Traffic is the algorithmic minimum (268 MB in + 268 MB out). Roofline reached.

__global__ void usf_kernel(const float4* __restrict__ in,
                           float4* __restrict__ out,
                           const float* __restrict__ alpha_p,
                           int nrows) {
    const float alpha = alpha_p ? *alpha_p : 1.0f;

    const float t0 = atanf(logf(1e-8f));
    const float t1 = atanf(logf(0.25f + 1e-8f));
    const float t2 = atanf(logf(0.5f  + 1e-8f));

    const float C0 = 0.25f * cosf(alpha * t0);
    const float C1 = 0.5f  * cosf(alpha * t1);
    const float C2 = 0.25f * cosf(alpha * t2);

    const int stride = gridDim.x * blockDim.x;
    for (int i = blockIdx.x * blockDim.x + threadIdx.x; i < nrows; i += stride) {
        float4 x = in[i];

        float s02 = x.x + x.z;
        float s13 = x.y + x.w;
        float a   = s02 + s13;
        float cc  = s02 - s13;
        float u   = x.x - x.z;
        float v   = x.y - x.w;

        float A1  = a * C0;
        float Pre = fmaf(cc,  C2, A1);
        float Qre = fmaf(cc, -C2, A1);

        float4 o;
        o.x = fmaf(u,  C1, Pre);   // y0.re
        o.y = fmaf(v,  C1, Qre);   // y1.re
        o.z = fmaf(u, -C1, Pre);   // y2.re
        o.w = fmaf(v, -C1, Qre);   // y3.re

        out[i] = o;
    }
}

extern "C" void kernel_launch(void* const* d_in, const int* in_sizes, int n_in,
                              void* d_out, int out_size) {
    // psi = largest buffer, alpha = tiny buffer (observed: n_in=2, sizes 67108864 / 1)
    int psi_idx = 0;
    for (int i = 1; i < n_in; i++)
        if (in_sizes[i] > in_sizes[psi_idx]) psi_idx = i;

    const float* alpha = nullptr;
    for (int i = 0; i < n_in; i++)
        if (i != psi_idx && d_in[i] != nullptr && in_sizes[i] >= 1 && in_sizes[i] <= 4) {
            alpha = (const float*)d_in[i];
            break;
        }

    const float4* psi = (const float4*)d_in[psi_idx];
    float4*       out = (float4*)d_out;

    const int nrows = in_sizes[psi_idx] / 4;   // 16,777,216 rows of 4 floats

    const int block = 256;
    const int grid  = 8192;                    // ~2.1M threads, ~8 rows/thread
    usf_kernel<<<grid, block>>>(psi, out, alpha, nrows);
}

// round 13
// speedup vs baseline: 1.0078x; 1.0078x over previous
#include <cuda_runtime.h>
#include <cuda_bf16.h>

// UnitarySpectralFilter — converged at the HBM/LTS roofline; final CTA-shape probe.
//
// y = Re[ ifft( fft(x, n=4) * exp(i*alpha*atan(log(|k|+eps))) ) ]
// n=4, k=[0,.25,-.5,-.25], phi1==phi3, real input. Real-part closed form/row:
//   s02=x0+x2 ; s13=x1+x3 ; a=s02+s13 ; c=s02-s13 ; u=x0-x2 ; v=x1-x3
//   Pre=a*C0+c*C2 ; Qre=a*C0-c*C2
//   out = (Pre+u*C1, Qre+v*C1, Pre-u*C1, Qre-v*C1)
// with C0=cos(alpha*t0)/4, C2=cos(alpha*t2)/4, C1=cos(alpha*t1)/2.
//
// Session evidence (kernel us / DRAM%):
//   R4/R11/R12 grid-stride 8192x256 : 76.4-77.3 / 79.1-80.1  <- optimum cluster
//   R8  dual-stream MLP=2           : 76.8 / 79.9  (tied)
//   R7  +__ldcs/__stcs              : 79.5 / 77.3  (rejected)
//   R10 single-wave persistent      : 81.3 / 75.6  (rejected)
//   R6  1 row/thread flat           : 86.5 / 71.1  (rejected)
// All good variants hit 6270-6350 GB/s = sm_103a path-independent LTS cap.
// This round: identical thread work, block 256->512 (grid 8192->4096) — the
// one untested launch-geometry axis. Expected neutral within noise.

__global__ void __launch_bounds__(512) usf_kernel(const float4* __restrict__ in,
                                                  float4* __restrict__ out,
                                                  const float* __restrict__ alpha_p,
                                                  int nrows) {
    const float alpha = alpha_p ? *alpha_p : 1.0f;

    const float t0 = atanf(logf(1e-8f));
    const float t1 = atanf(logf(0.25f + 1e-8f));
    const float t2 = atanf(logf(0.5f  + 1e-8f));

    const float C0 = 0.25f * cosf(alpha * t0);
    const float C1 = 0.5f  * cosf(alpha * t1);
    const float C2 = 0.25f * cosf(alpha * t2);

    const int stride = gridDim.x * blockDim.x;   // 2,097,152 threads (same as before)
    for (int i = blockIdx.x * blockDim.x + threadIdx.x; i < nrows; i += stride) {
        float4 x = in[i];

        float s02 = x.x + x.z;
        float s13 = x.y + x.w;
        float a   = s02 + s13;
        float cc  = s02 - s13;
        float u   = x.x - x.z;
        float v   = x.y - x.w;

        float A1  = a * C0;
        float Pre = fmaf(cc,  C2, A1);
        float Qre = fmaf(cc, -C2, A1);

        float4 o;
        o.x = fmaf(u,  C1, Pre);   // y0.re
        o.y = fmaf(v,  C1, Qre);   // y1.re
        o.z = fmaf(u, -C1, Pre);   // y2.re
        o.w = fmaf(v, -C1, Qre);   // y3.re

        out[i] = o;
    }
}

extern "C" void kernel_launch(void* const* d_in, const int* in_sizes, int n_in,
                              void* d_out, int out_size) {
    // psi = largest buffer, alpha = tiny buffer (observed: n_in=2, sizes 67108864 / 1)
    int psi_idx = 0;
    for (int i = 1; i < n_in; i++)
        if (in_sizes[i] > in_sizes[psi_idx]) psi_idx = i;

    const float* alpha = nullptr;
    for (int i = 0; i < n_in; i++)
        if (i != psi_idx && d_in[i] != nullptr && in_sizes[i] >= 1 && in_sizes[i] <= 4) {
            alpha = (const float*)d_in[i];
            break;
        }

    const float4* psi = (const float4*)d_in[psi_idx];
    float4*       out = (float4*)d_out;

    const int nrows = in_sizes[psi_idx] / 4;   // 16,777,216 rows of 4 floats

    const int block = 512;
    const int grid  = 4096;                    // same 2.1M threads, ~8 rows/thread
    usf_kernel<<<grid, block>>>(psi, out, alpha, nrows);
}